// round 3
// baseline (speedup 1.0000x reference)
#include <cuda_runtime.h>
#include <cuda_bf16.h>
#include <mma.h>
#include <math.h>

using namespace nvcuda;

// Problem shape constants
#define BATCHN   4
#define SEQ      1024
#define DMODEL   4096
#define NHEAD    32
#define HDIM     128
#define TOKENS   (BATCHN * SEQ)      // 4096
#define ROTARY_N 32
#define MAX_POS  10000

// ---------------------------------------------------------------------------
// Scratch (device globals; cudaMalloc is banned).
// NOTE: attention output O aliases g_q — Q is dead once the scores GEMM is
// done, and the PV GEMM reads only g_sc and g_v.
// ---------------------------------------------------------------------------
__device__ float g_q[(size_t)TOKENS * DMODEL];                      // 64 MB (later: O)
__device__ float g_k[(size_t)TOKENS * DMODEL];                      // 64 MB
__device__ float g_v[(size_t)TOKENS * DMODEL];                      // 64 MB
__device__ float g_sc[(size_t)BATCHN * NHEAD * SEQ * SEQ];          // 512 MB
__device__ float g_cos[SEQ * (ROTARY_N / 2)];
__device__ float g_sin[SEQ * (ROTARY_N / 2)];

// ---------------------------------------------------------------------------
// Rotary table: computed in double to match numpy float64 -> fp32 rounding
// ---------------------------------------------------------------------------
__global__ void rotary_table_kernel() {
    int idx = blockIdx.x * blockDim.x + threadIdx.x;
    if (idx >= SEQ * (ROTARY_N / 2)) return;
    int s = idx >> 4;          // 16 freqs per position
    int i = idx & 15;
    double inv = pow(10000.0, -((double)(2 * i)) / (double)ROTARY_N);
    double ang = (double)(MAX_POS - SEQ + s) * inv;
    g_cos[idx] = (float)cos(ang);
    g_sin[idx] = (float)sin(ang);
}

// ---------------------------------------------------------------------------
// Rotary apply (in-place on q and k, first 32 channels of each head).
// One thread owns a full (token, head) 32-channel group (avoids the
// read/write permutation race). 131072 threads.
// ---------------------------------------------------------------------------
__global__ void rotary_apply_kernel(float* __restrict__ q, float* __restrict__ k) {
    int idx = blockIdx.x * blockDim.x + threadIdx.x;
    if (idx >= TOKENS * NHEAD) return;
    int token = idx >> 5;
    int h     = idx & 31;
    int s     = token & (SEQ - 1);
    long long base = (long long)token * DMODEL + h * HDIM;
    const float* cs = g_cos + s * 16;
    const float* sn = g_sin + s * 16;

    float* ptrs[2] = {q, k};
#pragma unroll
    for (int w = 0; w < 2; w++) {
        float* p = ptrs[w] + base;
        float buf[32], out[32];
#pragma unroll
        for (int i = 0; i < 8; i++) ((float4*)buf)[i] = ((const float4*)p)[i];
#pragma unroll
        for (int i = 0; i < 16; i++) {
            float re = buf[i], im = buf[16 + i];
            float c = cs[i], sv = sn[i];
            out[2 * i]     = re * c - im * sv;
            out[2 * i + 1] = re * sv + im * c;
        }
#pragma unroll
        for (int i = 0; i < 8; i++) ((float4*)p)[i] = ((float4*)out)[i];
    }
}

// ---------------------------------------------------------------------------
// Generic batched TF32 wmma GEMM.
//   C[m][n] = scale * sum_k A[m][k] * B(k, n)  (+ biasN[n]) (+ bias2d[m][n])
// B_COL = true means B is accessed as B[n*ldb + k] (i.e., K^T from a row-major
// K tensor). All of M, N must be multiples of 128; K multiple of 32.
// Batch offset: z -> (z / nInner, z % nInner) with per-matrix stride pairs.
// CTA: 128x128 tile, 256 threads (8 warps as 2x4, warp tile 64x32),
// BK=32, double-buffered smem, epilogue staged through smem.
// ---------------------------------------------------------------------------
constexpr int BM = 128, BN = 128, BK = 32;
constexpr int ASTRIDE = 36;    // padded smem stride (floats), 144B (16B mult)
constexpr int BSTRIDE_ROW = 132;
constexpr int BUF_FLOATS = 4608;                  // 128*36
constexpr int SMEM_FLOATS = 4 * BUF_FLOATS;       // A0,B0,A1,B1
constexpr int SMEM_BYTES = SMEM_FLOATS * 4;       // 73728
constexpr int CB_STRIDE = 132;                    // epilogue staging stride

template <bool B_COL, bool HAS_BIASN, bool HAS_BIAS2D>
__global__ __launch_bounds__(256) void gemm_tf32_kernel(
    const float* __restrict__ A, int lda, long long outerA, long long innerA,
    const float* __restrict__ B, int ldb, long long outerB, long long innerB,
    float* __restrict__ C,       int ldc, long long outerC, long long innerC,
    int K, int nInner,
    const float* __restrict__ biasN,
    const float* __restrict__ bias2d, int ldBias2d,
    float scale)
{
    extern __shared__ float sm[];
    float* Abuf0 = sm;
    float* Bbuf0 = sm + BUF_FLOATS;
    float* Abuf1 = sm + 2 * BUF_FLOATS;
    float* Bbuf1 = sm + 3 * BUF_FLOATS;

    const int tid  = threadIdx.x;
    const int warp = tid >> 5;
    const int wm   = warp >> 2;   // 0..1
    const int wn   = warp & 3;    // 0..3
    const int m0   = blockIdx.y * BM;
    const int n0   = blockIdx.x * BN;

    {
        int z  = blockIdx.z;
        int zo = z / nInner;
        int zi = z - zo * nInner;
        A += (long long)zo * outerA + (long long)zi * innerA;
        B += (long long)zo * outerB + (long long)zi * innerB;
        C += (long long)zo * outerC + (long long)zi * innerC;
    }

    wmma::fragment<wmma::accumulator, 16, 16, 8, float> acc[4][2];
#pragma unroll
    for (int i = 0; i < 4; i++)
#pragma unroll
        for (int j = 0; j < 2; j++) wmma::fill_fragment(acc[i][j], 0.0f);

    const int nK = K / BK;

    auto load_tiles = [&](int kt, float* aDst, float* bDst) {
        const float* aSrc = A + (long long)m0 * lda + kt * BK;
#pragma unroll
        for (int i = 0; i < 4; i++) {
            int f = tid + i * 256;
            int r = f >> 3;
            int c = (f & 7) << 2;
            *(float4*)(aDst + r * ASTRIDE + c) =
                *(const float4*)(aSrc + (long long)r * lda + c);
        }
        if constexpr (B_COL) {
            const float* bSrc = B + (long long)n0 * ldb + kt * BK;
#pragma unroll
            for (int i = 0; i < 4; i++) {
                int f = tid + i * 256;
                int r = f >> 3;
                int c = (f & 7) << 2;
                *(float4*)(bDst + r * ASTRIDE + c) =
                    *(const float4*)(bSrc + (long long)r * ldb + c);
            }
        } else {
            const float* bSrc = B + (long long)kt * BK * ldb + n0;
#pragma unroll
            for (int i = 0; i < 4; i++) {
                int f = tid + i * 256;
                int r = f >> 5;
                int c = (f & 31) << 2;
                *(float4*)(bDst + r * BSTRIDE_ROW + c) =
                    *(const float4*)(bSrc + (long long)r * ldb + c);
            }
        }
    };

    load_tiles(0, Abuf0, Bbuf0);
    __syncthreads();

    for (int kt = 0; kt < nK; kt++) {
        const int cur = kt & 1;
        float* asw = cur ? Abuf1 : Abuf0;
        float* bsw = cur ? Bbuf1 : Bbuf0;
        if (kt + 1 < nK) load_tiles(kt + 1, cur ? Abuf0 : Abuf1, cur ? Bbuf0 : Bbuf1);
        const float* as = asw;
        const float* bs = bsw;

#pragma unroll
        for (int ks = 0; ks < 4; ks++) {
            wmma::fragment<wmma::matrix_a, 16, 16, 8, wmma::precision::tf32,
                           wmma::row_major> af[4];
#pragma unroll
            for (int i = 0; i < 4; i++) {
                wmma::load_matrix_sync(af[i], as + (wm * 64 + i * 16) * ASTRIDE + ks * 8,
                                       ASTRIDE);
#pragma unroll
                for (int e = 0; e < af[i].num_elements; e++)
                    af[i].x[e] = wmma::__float_to_tf32(af[i].x[e]);
            }
            if constexpr (B_COL) {
                wmma::fragment<wmma::matrix_b, 16, 16, 8, wmma::precision::tf32,
                               wmma::col_major> bf[2];
#pragma unroll
                for (int j = 0; j < 2; j++) {
                    wmma::load_matrix_sync(bf[j],
                                           bs + (wn * 32 + j * 16) * ASTRIDE + ks * 8,
                                           ASTRIDE);
#pragma unroll
                    for (int e = 0; e < bf[j].num_elements; e++)
                        bf[j].x[e] = wmma::__float_to_tf32(bf[j].x[e]);
                }
#pragma unroll
                for (int i = 0; i < 4; i++)
#pragma unroll
                    for (int j = 0; j < 2; j++)
                        wmma::mma_sync(acc[i][j], af[i], bf[j], acc[i][j]);
            } else {
                wmma::fragment<wmma::matrix_b, 16, 16, 8, wmma::precision::tf32,
                               wmma::row_major> bf[2];
#pragma unroll
                for (int j = 0; j < 2; j++) {
                    wmma::load_matrix_sync(bf[j],
                                           bs + ks * 8 * BSTRIDE_ROW + wn * 32 + j * 16,
                                           BSTRIDE_ROW);
#pragma unroll
                    for (int e = 0; e < bf[j].num_elements; e++)
                        bf[j].x[e] = wmma::__float_to_tf32(bf[j].x[e]);
                }
#pragma unroll
                for (int i = 0; i < 4; i++)
#pragma unroll
                    for (int j = 0; j < 2; j++)
                        wmma::mma_sync(acc[i][j], af[i], bf[j], acc[i][j]);
            }
        }
        __syncthreads();
    }

    // Epilogue: stage through smem, then fused scale/bias + coalesced store.
    float* cb = sm;
#pragma unroll
    for (int i = 0; i < 4; i++)
#pragma unroll
        for (int j = 0; j < 2; j++)
            wmma::store_matrix_sync(cb + (wm * 64 + i * 16) * CB_STRIDE + wn * 32 + j * 16,
                                    acc[i][j], CB_STRIDE, wmma::mem_row_major);
    __syncthreads();

    const float* b2 = HAS_BIAS2D ? (bias2d + (long long)m0 * ldBias2d + n0) : nullptr;
#pragma unroll
    for (int i = 0; i < 16; i++) {
        int f = tid + i * 256;
        int r = f >> 5;
        int c = (f & 31) << 2;
        float4 v = *(float4*)(cb + r * CB_STRIDE + c);
        v.x *= scale; v.y *= scale; v.z *= scale; v.w *= scale;
        if constexpr (HAS_BIASN) {
            float4 bn = *(const float4*)(biasN + n0 + c);
            v.x += bn.x; v.y += bn.y; v.z += bn.z; v.w += bn.w;
        }
        if constexpr (HAS_BIAS2D) {
            float4 bb = *(const float4*)(b2 + (long long)r * ldBias2d + c);
            v.x += bb.x; v.y += bb.y; v.z += bb.z; v.w += bb.w;
        }
        *(float4*)(C + (long long)(m0 + r) * ldc + n0 + c) = v;
    }
}

// ---------------------------------------------------------------------------
// Row softmax over 1024 elements; one 128-thread block per row.
// ---------------------------------------------------------------------------
__global__ void softmax_kernel(float* __restrict__ S) {
    __shared__ float red[8];
    const long long row = blockIdx.x;
    float* p = S + row * SEQ;
    const int t = threadIdx.x;

    float4 a = ((const float4*)p)[t];
    float4 b = ((const float4*)p)[t + 128];
    float m = fmaxf(fmaxf(fmaxf(a.x, a.y), fmaxf(a.z, a.w)),
                    fmaxf(fmaxf(b.x, b.y), fmaxf(b.z, b.w)));
#pragma unroll
    for (int o = 16; o > 0; o >>= 1) m = fmaxf(m, __shfl_xor_sync(0xffffffffu, m, o));
    if ((t & 31) == 0) red[t >> 5] = m;
    __syncthreads();
    m = fmaxf(fmaxf(red[0], red[1]), fmaxf(red[2], red[3]));

    a.x = expf(a.x - m); a.y = expf(a.y - m); a.z = expf(a.z - m); a.w = expf(a.w - m);
    b.x = expf(b.x - m); b.y = expf(b.y - m); b.z = expf(b.z - m); b.w = expf(b.w - m);
    float s = a.x + a.y + a.z + a.w + b.x + b.y + b.z + b.w;
#pragma unroll
    for (int o = 16; o > 0; o >>= 1) s += __shfl_xor_sync(0xffffffffu, s, o);
    if ((t & 31) == 0) red[4 + (t >> 5)] = s;
    __syncthreads();
    s = red[4] + red[5] + red[6] + red[7];
    float inv = 1.0f / s;

    a.x *= inv; a.y *= inv; a.z *= inv; a.w *= inv;
    b.x *= inv; b.y *= inv; b.z *= inv; b.w *= inv;
    ((float4*)p)[t]       = a;
    ((float4*)p)[t + 128] = b;
}

// ---------------------------------------------------------------------------
// Host launcher
// ---------------------------------------------------------------------------
extern "C" void kernel_launch(void* const* d_in, const int* in_sizes, int n_in,
                              void* d_out, int out_size) {
    (void)in_sizes; (void)n_in; (void)out_size;
    const float* x    = (const float*)d_in[0];
    const float* abia = (const float*)d_in[1];
    const float* wq   = (const float*)d_in[2];
    const float* bq   = (const float*)d_in[3];
    const float* wk   = (const float*)d_in[4];
    const float* bk   = (const float*)d_in[5];
    const float* wv   = (const float*)d_in[6];
    const float* bv   = (const float*)d_in[7];
    const float* wo   = (const float*)d_in[8];
    const float* bo   = (const float*)d_in[9];
    float* out = (float*)d_out;

    void* p;
    cudaGetSymbolAddress(&p, g_q);  float* q  = (float*)p;
    cudaGetSymbolAddress(&p, g_k);  float* k  = (float*)p;
    cudaGetSymbolAddress(&p, g_v);  float* v  = (float*)p;
    cudaGetSymbolAddress(&p, g_sc); float* sc = (float*)p;
    float* o = q;   // alias: Q is dead after the scores GEMM

    cudaFuncSetAttribute(gemm_tf32_kernel<false, true,  false>,
                         cudaFuncAttributeMaxDynamicSharedMemorySize, SMEM_BYTES);
    cudaFuncSetAttribute(gemm_tf32_kernel<true,  false, true>,
                         cudaFuncAttributeMaxDynamicSharedMemorySize, SMEM_BYTES);
    cudaFuncSetAttribute(gemm_tf32_kernel<false, false, false>,
                         cudaFuncAttributeMaxDynamicSharedMemorySize, SMEM_BYTES);

    // 1) Rotary tables
    rotary_table_kernel<<<(SEQ * 16 + 255) / 256, 256>>>();

    // 2) QKV projections: [4096,4096] x [4096,4096] + bias
    {
        dim3 grid(DMODEL / BN, TOKENS / BM, 1);
        gemm_tf32_kernel<false, true, false><<<grid, 256, SMEM_BYTES>>>(
            x, DMODEL, 0, 0, wq, DMODEL, 0, 0, q, DMODEL, 0, 0,
            DMODEL, 1, bq, nullptr, 0, 1.0f);
        gemm_tf32_kernel<false, true, false><<<grid, 256, SMEM_BYTES>>>(
            x, DMODEL, 0, 0, wk, DMODEL, 0, 0, k, DMODEL, 0, 0,
            DMODEL, 1, bk, nullptr, 0, 1.0f);
        gemm_tf32_kernel<false, true, false><<<grid, 256, SMEM_BYTES>>>(
            x, DMODEL, 0, 0, wv, DMODEL, 0, 0, v, DMODEL, 0, 0,
            DMODEL, 1, bv, nullptr, 0, 1.0f);
    }

    // 3) Rotary on q, k
    rotary_apply_kernel<<<(TOKENS * NHEAD + 255) / 256, 256>>>(q, k);

    // 4) Scores: S[bh] = Q_bh * K_bh^T / sqrt(HD) + attn_bias
    {
        dim3 grid(SEQ / BN, SEQ / BM, BATCHN * NHEAD);
        const long long tokD = (long long)SEQ * DMODEL;      // per-batch A/B stride
        const long long scO  = (long long)NHEAD * SEQ * SEQ; // per-batch C stride
        gemm_tf32_kernel<true, false, true><<<grid, 256, SMEM_BYTES>>>(
            q, DMODEL, tokD, HDIM,
            k, DMODEL, tokD, HDIM,
            sc, SEQ, scO, (long long)SEQ * SEQ,
            HDIM, NHEAD,
            nullptr, abia, SEQ, 0.08838834764831845f);
    }

    // 5) Softmax over rows
    softmax_kernel<<<BATCHN * NHEAD * SEQ, 128>>>(sc);

    // 6) O = P * V   (O aliases g_q; Q no longer needed)
    {
        dim3 grid(HDIM / BN, SEQ / BM, BATCHN * NHEAD);
        const long long tokD = (long long)SEQ * DMODEL;
        const long long scO  = (long long)NHEAD * SEQ * SEQ;
        gemm_tf32_kernel<false, false, false><<<grid, 256, SMEM_BYTES>>>(
            sc, SEQ, scO, (long long)SEQ * SEQ,
            v, DMODEL, tokD, HDIM,
            o, DMODEL, tokD, HDIM,
            SEQ, NHEAD,
            nullptr, nullptr, 0, 1.0f);
    }

    // 7) Output projection: out = O * Wo + bo
    {
        dim3 grid(DMODEL / BN, TOKENS / BM, 1);
        gemm_tf32_kernel<false, true, false><<<grid, 256, SMEM_BYTES>>>(
            o, DMODEL, 0, 0, wo, DMODEL, 0, 0, out, DMODEL, 0, 0,
            DMODEL, 1, bo, nullptr, 0, 1.0f);
    }
}

// round 5
// speedup vs baseline: 2.8885x; 2.8885x over previous
#include <cuda_runtime.h>
#include <cstdint>
#include <math.h>

#define BATCHN 4
#define SEQ    1024
#define DMODEL 4096
#define NHEAD  32
#define HDIM   128
#define TOKENS 4096
#define MAX_POS 10000

// ---------------- scratch (device globals; malloc banned) ------------------
__device__ float g_xr [(size_t)TOKENS * DMODEL];    // tf32-rounded, k-permuted x (later: o_r)
__device__ float g_wqr[(size_t)DMODEL * DMODEL];
__device__ float g_wkr[(size_t)DMODEL * DMODEL];
__device__ float g_wvr[(size_t)DMODEL * DMODEL];
__device__ float g_wor[(size_t)DMODEL * DMODEL];
__device__ float g_q  [(size_t)TOKENS * DMODEL];    // plain q (later: attention out o)
__device__ float g_k  [(size_t)TOKENS * DMODEL];
__device__ float g_v  [(size_t)TOKENS * DMODEL];
__device__ float g_qr [(size_t)TOKENS * DMODEL];
__device__ float g_kr [(size_t)TOKENS * DMODEL];
__device__ float g_vt [(size_t)BATCHN * NHEAD * HDIM * SEQ];
__device__ float g_sc [(size_t)BATCHN * NHEAD * SEQ * SEQ];   // 512MB
__device__ float g_cos[SEQ * 16];
__device__ float g_sin[SEQ * 16];

// ---------------- helpers ---------------------------------------------------
__device__ __forceinline__ uint32_t su32(const void* p) {
    return (uint32_t)__cvta_generic_to_shared(p);
}
__device__ __forceinline__ float tf32r(float x) {
    uint32_t u;
    asm("cvt.rna.tf32.f32 %0, %1;" : "=r"(u) : "f"(x));
    return __uint_as_float(u);
}
// permuted column: within each 16-group, orig col k stored at 4*(k%4) + (k%16)/4
__device__ __forceinline__ int permc(int k) {
    int kk = k & 15;
    return (k & ~15) | ((kk & 3) << 2) | (kk >> 2);
}
__device__ __forceinline__ void cpa(uint32_t s, const void* g) {
    asm volatile("cp.async.cg.shared.global [%0], [%1], 16;" :: "r"(s), "l"(g));
}
__device__ __forceinline__ void cpa_commit() {
    asm volatile("cp.async.commit_group;" ::: "memory");
}
template <int N> __device__ __forceinline__ void cpa_wait() {
    asm volatile("cp.async.wait_group %0;" :: "n"(N) : "memory");
}
__device__ __forceinline__ void lds4(uint32_t* v, uint32_t a) {
    asm volatile("ld.shared.v4.b32 {%0,%1,%2,%3}, [%4];"
                 : "=r"(v[0]), "=r"(v[1]), "=r"(v[2]), "=r"(v[3]) : "r"(a));
}
__device__ __forceinline__ void mma8(float* c, uint32_t a0, uint32_t a1, uint32_t a2,
                                     uint32_t a3, uint32_t b0, uint32_t b1) {
    asm volatile(
        "mma.sync.aligned.m16n8k8.row.col.f32.tf32.tf32.f32 "
        "{%0,%1,%2,%3},{%4,%5,%6,%7},{%8,%9},{%0,%1,%2,%3};"
        : "+f"(c[0]), "+f"(c[1]), "+f"(c[2]), "+f"(c[3])
        : "r"(a0), "r"(a1), "r"(a2), "r"(a3), "r"(b0), "r"(b1));
}

// ---------------------------------------------------------------------------
// TF32 mma.sync GEMM. A: [M][lda] k-permuted tf32. B: [N][ldb] k-permuted tf32
// (row n holds B(n, k) i.e. N-major). C[m][n] = sum_k A*B, post-op per EPI:
//   0: plain fp32   1: + biasN[n]   2: * scale + bias2d[m][n]
// CTA 128x128, BK=32, 3-stage cp.async, 8 warps (2x4) of 64x32.
// Smem: tight 128B rows, chunk swizzle c ^= (row&1)*4.
// ---------------------------------------------------------------------------
constexpr int STAGES = 3;
constexpr int SMEM_GEMM = STAGES * 32768;   // 96KB

template <int EPI>
__global__ __launch_bounds__(256, 2) void gemm_kernel(
    const float* __restrict__ A, int lda, long long outerA, long long innerA,
    const float* __restrict__ B, int ldb, long long outerB, long long innerB,
    float* __restrict__ C, int ldc, long long outerC, long long innerC,
    int K, int nInner,
    const float* __restrict__ biasN,
    const float* __restrict__ bias2d, int ldb2, float scale)
{
    extern __shared__ float sm[];
    const uint32_t sb = su32(sm);
    const int tid = threadIdx.x, wid = tid >> 5, l = tid & 31;
    const int wm = wid >> 2, wn = wid & 3;
    const int m0 = blockIdx.y * 128, n0 = blockIdx.x * 128;
    const int z = blockIdx.z, zo = z / nInner, zi = z - zo * nInner;

    A += zo * outerA + zi * innerA + (long long)m0 * lda;
    B += zo * outerB + zi * innerB + (long long)n0 * ldb;
    C += zo * outerC + zi * innerC;

    float acc[4][4][4] = {};

    const int nK = K / 32;

    auto fill = [&](int kt, int s) {
        const uint32_t ab = sb + s * 32768;
        const float* ag = A + kt * 32;
        const float* bg = B + kt * 32;
#pragma unroll
        for (int i = 0; i < 4; i++) {
            int ch = tid + i * 256, r = ch >> 3, c = ch & 7;
            cpa(ab + r * 128 + ((c ^ ((r & 1) << 2)) << 4),
                ag + (long long)r * lda + c * 4);
        }
#pragma unroll
        for (int i = 0; i < 4; i++) {
            int ch = tid + i * 256, r = ch >> 3, c = ch & 7;
            cpa(ab + 16384 + r * 128 + ((c ^ ((r & 1) << 2)) << 4),
                bg + (long long)r * ldb + c * 4);
        }
        cpa_commit();
    };

    for (int s = 0; s < STAGES - 1; s++) fill(s, s);

    for (int kt = 0; kt < nK; kt++) {
        cpa_wait<STAGES - 2>();
        __syncthreads();
        if (kt + STAGES - 1 < nK) fill(kt + STAGES - 1, (kt + STAGES - 1) % STAGES);
        else cpa_commit();

        const uint32_t ab = sb + (kt % STAGES) * 32768;
        const uint32_t bb = ab + 16384;
#pragma unroll
        for (int g = 0; g < 2; g++) {
            uint32_t bfr[4][4];
#pragma unroll
            for (int nt = 0; nt < 4; nt++) {
                int r = wn * 32 + nt * 8 + (l >> 2);
                lds4(bfr[nt], bb + r * 128 + (((g * 4 + (l & 3)) ^ ((r & 1) << 2)) << 4));
            }
#pragma unroll
            for (int mt = 0; mt < 4; mt++) {
                int r0 = wm * 64 + mt * 16 + (l >> 2);
                int r1 = r0 + 8;
                uint32_t a0[4], a1[4];
                lds4(a0, ab + r0 * 128 + (((g * 4 + (l & 3)) ^ ((r0 & 1) << 2)) << 4));
                lds4(a1, ab + r1 * 128 + (((g * 4 + (l & 3)) ^ ((r1 & 1) << 2)) << 4));
#pragma unroll
                for (int nt = 0; nt < 4; nt++)
                    mma8(acc[mt][nt], a0[0], a1[0], a0[1], a1[1], bfr[nt][0], bfr[nt][1]);
#pragma unroll
                for (int nt = 0; nt < 4; nt++)
                    mma8(acc[mt][nt], a0[2], a1[2], a0[3], a1[3], bfr[nt][2], bfr[nt][3]);
            }
        }
    }

    // epilogue
#pragma unroll
    for (int mt = 0; mt < 4; mt++)
#pragma unroll
        for (int h = 0; h < 2; h++) {
            const long long row = m0 + wm * 64 + mt * 16 + (l >> 2) + h * 8;
            float* cr = C + row * ldc;
            const float* b2r = (EPI == 2) ? (bias2d + row * ldb2) : nullptr;
#pragma unroll
            for (int nt = 0; nt < 4; nt++) {
                int col = n0 + wn * 32 + nt * 8 + (l & 3) * 2;
                float v0 = acc[mt][nt][2 * h], v1 = acc[mt][nt][2 * h + 1];
                if (EPI == 2) { v0 = v0 * scale + b2r[col]; v1 = v1 * scale + b2r[col + 1]; }
                if (EPI == 1) { v0 += biasN[col]; v1 += biasN[col + 1]; }
                float2 o = {v0, v1};
                *(float2*)(cr + col) = o;
            }
        }
}

// ---------------- prep / aux kernels ----------------------------------------
__global__ void rotary_table_kernel() {
    int idx = blockIdx.x * blockDim.x + threadIdx.x;
    if (idx >= SEQ * 16) return;
    int s = idx >> 4, i = idx & 15;
    double inv = pow(10000.0, -((double)(2 * i)) / 32.0);
    double ang = (double)(MAX_POS - SEQ + s) * inv;
    g_cos[idx] = (float)cos(ang);
    g_sin[idx] = (float)sin(ang);
}

// round + permute rows: [R][4096] -> [R][4096 perm]
__global__ void rp_kernel(const float* __restrict__ in, float* __restrict__ out, int n4) {
    int i = blockIdx.x * blockDim.x + threadIdx.x;
    if (i >= n4) return;
    int r = i >> 10, c = (i & 1023) * 4;
    float4 v = *(const float4*)(in + (long long)r * 4096 + c);
    float* o = out + (long long)r * 4096;
    o[permc(c)]     = tf32r(v.x);
    o[permc(c + 1)] = tf32r(v.y);
    o[permc(c + 2)] = tf32r(v.z);
    o[permc(c + 3)] = tf32r(v.w);
}

// weight [k 4096][n 4096] -> [n][4096 perm k], rounded
__global__ void wt_kernel(const float* __restrict__ w, float* __restrict__ out) {
    __shared__ float t[32][33];
    int k0 = blockIdx.y * 32, n0 = blockIdx.x * 32;
    int tx = threadIdx.x, ty = threadIdx.y;
#pragma unroll
    for (int i = 0; i < 4; i++)
        t[ty + i * 8][tx] = w[(long long)(k0 + ty + i * 8) * 4096 + n0 + tx];
    __syncthreads();
#pragma unroll
    for (int i = 0; i < 4; i++) {
        int n = n0 + ty + i * 8, k = k0 + tx;
        out[(long long)n * 4096 + permc(k)] = tf32r(t[tx][ty + i * 8]);
    }
}

// rotary (first 32 ch/head) + round + permute for q and k
__global__ void rrp_kernel(const float* __restrict__ q, const float* __restrict__ k,
                           float* __restrict__ qr, float* __restrict__ kr) {
    int idx = blockIdx.x * blockDim.x + threadIdx.x;
    if (idx >= TOKENS * NHEAD) return;
    int tok = idx >> 5, h = idx & 31;
    int s = tok & (SEQ - 1);
    long long base = (long long)tok * DMODEL + h * HDIM;
    const float* cs = g_cos + s * 16;
    const float* sn = g_sin + s * 16;

    const float* ins[2]  = {q, k};
    float*       outs[2] = {qr, kr};
#pragma unroll
    for (int w = 0; w < 2; w++) {
        const float* p = ins[w] + base;
        float* o = outs[w] + base;
        float buf[32];
#pragma unroll
        for (int i = 0; i < 8; i++) ((float4*)buf)[i] = ((const float4*)p)[i];
#pragma unroll
        for (int i = 0; i < 16; i++) {
            float c = cs[i], sv = sn[i];
            float re = buf[i], im = buf[16 + i];
            o[permc(2 * i)]     = tf32r(re * c - im * sv);
            o[permc(2 * i + 1)] = tf32r(re * sv + im * c);
        }
        for (int j = 32; j < 128; j += 4) {
            float4 v = *(const float4*)(p + j);
            o[permc(j)]     = tf32r(v.x);
            o[permc(j + 1)] = tf32r(v.y);
            o[permc(j + 2)] = tf32r(v.z);
            o[permc(j + 3)] = tf32r(v.w);
        }
    }
}

// v plain [tok][4096] -> vt [bh][d 128][s 1024 perm], rounded
__global__ void vtr_kernel(const float* __restrict__ v, float* __restrict__ vt) {
    __shared__ float t[32][33];
    int bh = blockIdx.z, b = bh >> 5, h = bh & 31;
    int s0 = blockIdx.x * 32, d0 = blockIdx.y * 32;
    int tx = threadIdx.x, ty = threadIdx.y;
    const float* src = v + (long long)b * SEQ * DMODEL + h * HDIM;
#pragma unroll
    for (int i = 0; i < 4; i++)
        t[ty + i * 8][tx] = src[(long long)(s0 + ty + i * 8) * DMODEL + d0 + tx];
    __syncthreads();
    float* dst = vt + (long long)bh * HDIM * SEQ;
#pragma unroll
    for (int i = 0; i < 4; i++) {
        int d = d0 + ty + i * 8, s = s0 + tx;
        dst[(long long)d * SEQ + permc(s)] = tf32r(t[tx][ty + i * 8]);
    }
}

// row softmax over 1024, write rounded + k-permuted in place
__global__ void softmax_kernel(float* __restrict__ S) {
    __shared__ float red[8];
    float* p = S + (long long)blockIdx.x * SEQ;
    const int t = threadIdx.x;
    float4 a = ((const float4*)p)[t];
    float4 b = ((const float4*)p)[t + 128];
    float m = fmaxf(fmaxf(fmaxf(a.x, a.y), fmaxf(a.z, a.w)),
                    fmaxf(fmaxf(b.x, b.y), fmaxf(b.z, b.w)));
#pragma unroll
    for (int o = 16; o > 0; o >>= 1) m = fmaxf(m, __shfl_xor_sync(~0u, m, o));
    if ((t & 31) == 0) red[t >> 5] = m;
    __syncthreads();
    m = fmaxf(fmaxf(red[0], red[1]), fmaxf(red[2], red[3]));
    a.x = expf(a.x - m); a.y = expf(a.y - m); a.z = expf(a.z - m); a.w = expf(a.w - m);
    b.x = expf(b.x - m); b.y = expf(b.y - m); b.z = expf(b.z - m); b.w = expf(b.w - m);
    float s = a.x + a.y + a.z + a.w + b.x + b.y + b.z + b.w;
#pragma unroll
    for (int o = 16; o > 0; o >>= 1) s += __shfl_xor_sync(~0u, s, o);
    if ((t & 31) == 0) red[4 + (t >> 5)] = s;
    __syncthreads();
    s = red[4] + red[5] + red[6] + red[7];
    float inv = 1.0f / s;
    float vals[8] = {a.x * inv, a.y * inv, a.z * inv, a.w * inv,
                     b.x * inv, b.y * inv, b.z * inv, b.w * inv};
    __syncthreads();   // all reads complete before permuted overwrite
    int c0[2] = {t * 4, 512 + t * 4};
#pragma unroll
    for (int g = 0; g < 2; g++)
#pragma unroll
        for (int i = 0; i < 4; i++)
            p[permc(c0[g] + i)] = tf32r(vals[g * 4 + i]);
}

// ---------------- host ------------------------------------------------------
extern "C" void kernel_launch(void* const* d_in, const int* in_sizes, int n_in,
                              void* d_out, int out_size) {
    (void)in_sizes; (void)n_in; (void)out_size;
    const float* x    = (const float*)d_in[0];
    const float* abia = (const float*)d_in[1];
    const float* wq   = (const float*)d_in[2];
    const float* bq   = (const float*)d_in[3];
    const float* wk   = (const float*)d_in[4];
    const float* bk   = (const float*)d_in[5];
    const float* wv   = (const float*)d_in[6];
    const float* bv   = (const float*)d_in[7];
    const float* wo   = (const float*)d_in[8];
    const float* bo   = (const float*)d_in[9];
    float* out = (float*)d_out;

    void* p;
    cudaGetSymbolAddress(&p, g_xr);  float* xr  = (float*)p;
    cudaGetSymbolAddress(&p, g_wqr); float* wqr = (float*)p;
    cudaGetSymbolAddress(&p, g_wkr); float* wkr = (float*)p;
    cudaGetSymbolAddress(&p, g_wvr); float* wvr = (float*)p;
    cudaGetSymbolAddress(&p, g_wor); float* wor = (float*)p;
    cudaGetSymbolAddress(&p, g_q);   float* q   = (float*)p;
    cudaGetSymbolAddress(&p, g_k);   float* k   = (float*)p;
    cudaGetSymbolAddress(&p, g_v);   float* v   = (float*)p;
    cudaGetSymbolAddress(&p, g_qr);  float* qr  = (float*)p;
    cudaGetSymbolAddress(&p, g_kr);  float* kr  = (float*)p;
    cudaGetSymbolAddress(&p, g_vt);  float* vt  = (float*)p;
    cudaGetSymbolAddress(&p, g_sc);  float* sc  = (float*)p;
    float* o  = q;    // q plain dead after rrp -> reuse for attention out
    float* orr = xr;  // xr dead after QKV -> reuse for rounded o

    cudaFuncSetAttribute(gemm_kernel<0>, cudaFuncAttributeMaxDynamicSharedMemorySize, SMEM_GEMM);
    cudaFuncSetAttribute(gemm_kernel<1>, cudaFuncAttributeMaxDynamicSharedMemorySize, SMEM_GEMM);
    cudaFuncSetAttribute(gemm_kernel<2>, cudaFuncAttributeMaxDynamicSharedMemorySize, SMEM_GEMM);

    rotary_table_kernel<<<(SEQ * 16 + 255) / 256, 256>>>();
    rp_kernel<<<(TOKENS * 1024 + 255) / 256, 256>>>(x, xr, TOKENS * 1024);
    {
        dim3 g(128, 128), b(32, 8);
        wt_kernel<<<g, b>>>(wq, wqr);
        wt_kernel<<<g, b>>>(wk, wkr);
        wt_kernel<<<g, b>>>(wv, wvr);
        wt_kernel<<<g, b>>>(wo, wor);
    }

    // QKV projections
    {
        dim3 grid(32, 32, 1);
        gemm_kernel<1><<<grid, 256, SMEM_GEMM>>>(
            xr, DMODEL, 0, 0, wqr, DMODEL, 0, 0, q, DMODEL, 0, 0,
            DMODEL, 1, bq, nullptr, 0, 1.0f);
        gemm_kernel<1><<<grid, 256, SMEM_GEMM>>>(
            xr, DMODEL, 0, 0, wkr, DMODEL, 0, 0, k, DMODEL, 0, 0,
            DMODEL, 1, bk, nullptr, 0, 1.0f);
        gemm_kernel<1><<<grid, 256, SMEM_GEMM>>>(
            xr, DMODEL, 0, 0, wvr, DMODEL, 0, 0, v, DMODEL, 0, 0,
            DMODEL, 1, bv, nullptr, 0, 1.0f);
    }

    rrp_kernel<<<(TOKENS * NHEAD + 255) / 256, 256>>>(q, k, qr, kr);
    vtr_kernel<<<dim3(32, 4, BATCHN * NHEAD), dim3(32, 8)>>>(v, vt);

    // scores: per (b,h) [1024x1024] = Q K^T * scale + attn_bias
    gemm_kernel<2><<<dim3(8, 8, BATCHN * NHEAD), 256, SMEM_GEMM>>>(
        qr, DMODEL, (long long)SEQ * DMODEL, HDIM,
        kr, DMODEL, (long long)SEQ * DMODEL, HDIM,
        sc, SEQ, (long long)NHEAD * SEQ * SEQ, (long long)SEQ * SEQ,
        HDIM, NHEAD, nullptr, abia, SEQ, 0.08838834764831845f);

    softmax_kernel<<<BATCHN * NHEAD * SEQ, 128>>>(sc);

    // PV: per (b,h) [1024 x 128] (o aliases g_q)
    gemm_kernel<0><<<dim3(1, 8, BATCHN * NHEAD), 256, SMEM_GEMM>>>(
        sc, SEQ, (long long)NHEAD * SEQ * SEQ, (long long)SEQ * SEQ,
        vt, SEQ, (long long)NHEAD * HDIM * SEQ, (long long)HDIM * SEQ,
        o, DMODEL, (long long)SEQ * DMODEL, HDIM,
        SEQ, NHEAD, nullptr, nullptr, 0, 1.0f);

    // out projection
    rp_kernel<<<(TOKENS * 1024 + 255) / 256, 256>>>(o, orr, TOKENS * 1024);
    gemm_kernel<1><<<dim3(32, 32, 1), 256, SMEM_GEMM>>>(
        orr, DMODEL, 0, 0, wor, DMODEL, 0, 0, out, DMODEL, 0, 0,
        DMODEL, 1, bo, nullptr, 0, 1.0f);
}

// round 6
// speedup vs baseline: 3.2175x; 1.1139x over previous
#include <cuda_runtime.h>
#include <cstdint>
#include <math.h>

#define BATCHN 4
#define SEQ    1024
#define DMODEL 4096
#define NHEAD  32
#define HDIM   128
#define TOKENS 4096
#define MAX_POS 10000

// ---------------- scratch (device globals; malloc banned) ------------------
__device__ float g_xr [(size_t)TOKENS * DMODEL];    // rounded/permuted x (later: flash O out)
__device__ float g_wqr[(size_t)DMODEL * DMODEL];
__device__ float g_wkr[(size_t)DMODEL * DMODEL];
__device__ float g_wvr[(size_t)DMODEL * DMODEL];
__device__ float g_wor[(size_t)DMODEL * DMODEL];
__device__ float g_qr [(size_t)TOKENS * DMODEL];    // rotary+rounded+permuted Q
__device__ float g_kr [(size_t)TOKENS * DMODEL];
__device__ float g_v  [(size_t)TOKENS * DMODEL];    // plain V
__device__ float g_vt [(size_t)BATCHN * NHEAD * HDIM * SEQ];  // V^T rounded/permuted
__device__ float g_cos[SEQ * 16];
__device__ float g_sin[SEQ * 16];

// ---------------- helpers ---------------------------------------------------
__device__ __forceinline__ uint32_t su32(const void* p) {
    return (uint32_t)__cvta_generic_to_shared(p);
}
__device__ __forceinline__ float tf32r(float x) {
    uint32_t u;
    asm("cvt.rna.tf32.f32 %0, %1;" : "=r"(u) : "f"(x));
    return __uint_as_float(u);
}
// permuted column: within each 16-group, col k stored at 4*(k%4) + (k%16)/4
__device__ __forceinline__ int permc(int k) {
    int kk = k & 15;
    return (k & ~15) | ((kk & 3) << 2) | (kk >> 2);
}
__device__ __forceinline__ void cpa(uint32_t s, const void* g) {
    asm volatile("cp.async.cg.shared.global [%0], [%1], 16;" :: "r"(s), "l"(g));
}
__device__ __forceinline__ void cpa_commit() {
    asm volatile("cp.async.commit_group;" ::: "memory");
}
template <int N> __device__ __forceinline__ void cpa_wait() {
    asm volatile("cp.async.wait_group %0;" :: "n"(N) : "memory");
}
__device__ __forceinline__ void lds4(uint32_t* v, uint32_t a) {
    asm volatile("ld.shared.v4.b32 {%0,%1,%2,%3}, [%4];"
                 : "=r"(v[0]), "=r"(v[1]), "=r"(v[2]), "=r"(v[3]) : "r"(a));
}
__device__ __forceinline__ void mma8(float* c, uint32_t a0, uint32_t a1, uint32_t a2,
                                     uint32_t a3, uint32_t b0, uint32_t b1) {
    asm volatile(
        "mma.sync.aligned.m16n8k8.row.col.f32.tf32.tf32.f32 "
        "{%0,%1,%2,%3},{%4,%5,%6,%7},{%8,%9},{%0,%1,%2,%3};"
        : "+f"(c[0]), "+f"(c[1]), "+f"(c[2]), "+f"(c[3])
        : "r"(a0), "r"(a1), "r"(a2), "r"(a3), "r"(b0), "r"(b1));
}

// shared 128x128x32 warp-tile mma core: A tile at ab, B tile at bb (both
// [rows][32 floats] with 16B-chunk swizzle). 8 warps 2x4, warp 64x32.
__device__ __forceinline__ void mma_core(uint32_t ab, uint32_t bb,
                                         float acc[4][4][4], int wm, int wn, int l) {
#pragma unroll
    for (int g = 0; g < 2; g++) {
        uint32_t bfr[4][4];
#pragma unroll
        for (int nt = 0; nt < 4; nt++) {
            int r = wn * 32 + nt * 8 + (l >> 2);
            lds4(bfr[nt], bb + r * 128 + (((g * 4 + (l & 3)) ^ ((r & 1) << 2)) << 4));
        }
#pragma unroll
        for (int mt = 0; mt < 4; mt++) {
            int r0 = wm * 64 + mt * 16 + (l >> 2), r1 = r0 + 8;
            uint32_t a0[4], a1[4];
            lds4(a0, ab + r0 * 128 + (((g * 4 + (l & 3)) ^ ((r0 & 1) << 2)) << 4));
            lds4(a1, ab + r1 * 128 + (((g * 4 + (l & 3)) ^ ((r1 & 1) << 2)) << 4));
#pragma unroll
            for (int nt = 0; nt < 4; nt++)
                mma8(acc[mt][nt], a0[0], a1[0], a0[1], a1[1], bfr[nt][0], bfr[nt][1]);
#pragma unroll
            for (int nt = 0; nt < 4; nt++)
                mma8(acc[mt][nt], a0[2], a1[2], a0[3], a1[3], bfr[nt][2], bfr[nt][3]);
        }
    }
}

// ---------------------------------------------------------------------------
// TF32 mma.sync GEMM (unchanged core). EPI: 1 = fp32 + biasN store.
// EPI 3 = QK path: + biasN, rotary on first 32 cols of each 128-head,
//         tf32 round + permc store (feeds flash / next GEMM directly).
// ---------------------------------------------------------------------------
constexpr int STAGES = 3;
constexpr int SMEM_GEMM = STAGES * 32768;   // 96KB

template <int EPI>
__global__ __launch_bounds__(256, 2) void gemm_kernel(
    const float* __restrict__ A, int lda,
    const float* __restrict__ B, int ldb,
    float* __restrict__ C, int ldc,
    int K, const float* __restrict__ biasN)
{
    extern __shared__ float sm[];
    const uint32_t sb = su32(sm);
    const int tid = threadIdx.x, wid = tid >> 5, l = tid & 31;
    const int wm = wid >> 2, wn = wid & 3;
    const int m0 = blockIdx.y * 128, n0 = blockIdx.x * 128;

    A += (long long)m0 * lda;
    B += (long long)n0 * ldb;

    float acc[4][4][4] = {};
    const int nK = K / 32;

    auto fill = [&](int kt, int s) {
        const uint32_t ab = sb + s * 32768;
        const float* ag = A + kt * 32;
        const float* bg = B + kt * 32;
#pragma unroll
        for (int i = 0; i < 4; i++) {
            int ch = tid + i * 256, r = ch >> 3, c = ch & 7;
            cpa(ab + r * 128 + ((c ^ ((r & 1) << 2)) << 4),
                ag + (long long)r * lda + c * 4);
        }
#pragma unroll
        for (int i = 0; i < 4; i++) {
            int ch = tid + i * 256, r = ch >> 3, c = ch & 7;
            cpa(ab + 16384 + r * 128 + ((c ^ ((r & 1) << 2)) << 4),
                bg + (long long)r * ldb + c * 4);
        }
        cpa_commit();
    };

    for (int s = 0; s < STAGES - 1; s++) fill(s, s);

    for (int kt = 0; kt < nK; kt++) {
        cpa_wait<STAGES - 2>();
        __syncthreads();
        if (kt + STAGES - 1 < nK) fill(kt + STAGES - 1, (kt + STAGES - 1) % STAGES);
        else cpa_commit();
        const uint32_t ab = sb + (kt % STAGES) * 32768;
        mma_core(ab, ab + 16384, acc, wm, wn, l);
        __syncthreads();
    }

#pragma unroll
    for (int mt = 0; mt < 4; mt++)
#pragma unroll
        for (int h = 0; h < 2; h++) {
            const long long row = m0 + wm * 64 + mt * 16 + (l >> 2) + h * 8;
            float* cr = C + row * ldc;
            if (EPI == 1) {
#pragma unroll
                for (int nt = 0; nt < 4; nt++) {
                    int col = n0 + wn * 32 + nt * 8 + (l & 3) * 2;
                    float2 o = {acc[mt][nt][2 * h] + biasN[col],
                                acc[mt][nt][2 * h + 1] + biasN[col + 1]};
                    *(float2*)(cr + col) = o;
                }
            } else {  // EPI 3
                if (wn == 0) {
                    const int tok = (int)(row & (SEQ - 1));
                    const float* cs = g_cos + tok * 16;
                    const float* sn = g_sin + tok * 16;
#pragma unroll
                    for (int nt = 0; nt < 2; nt++) {
                        int i = nt * 8 + (l & 3) * 2;       // head-local re col, even
                        int colr = n0 + i;
                        float re0 = acc[mt][nt][2 * h]     + biasN[colr];
                        float re1 = acc[mt][nt][2 * h + 1] + biasN[colr + 1];
                        float im0 = acc[mt][nt + 2][2 * h]     + biasN[colr + 16];
                        float im1 = acc[mt][nt + 2][2 * h + 1] + biasN[colr + 17];
                        float c0 = cs[i], s0 = sn[i], c1 = cs[i + 1], s1 = sn[i + 1];
                        int ob = n0 + 2 * i;
                        cr[permc(ob)]     = tf32r(re0 * c0 - im0 * s0);
                        cr[permc(ob + 1)] = tf32r(re0 * s0 + im0 * c0);
                        cr[permc(ob + 2)] = tf32r(re1 * c1 - im1 * s1);
                        cr[permc(ob + 3)] = tf32r(re1 * s1 + im1 * c1);
                    }
                } else {
#pragma unroll
                    for (int nt = 0; nt < 4; nt++) {
                        int col = n0 + wn * 32 + nt * 8 + (l & 3) * 2;
                        cr[permc(col)]     = tf32r(acc[mt][nt][2 * h] + biasN[col]);
                        cr[permc(col + 1)] = tf32r(acc[mt][nt][2 * h + 1] + biasN[col + 1]);
                    }
                }
            }
        }
}

// ---------------------------------------------------------------------------
// Flash attention: per CTA one (b,h) and 128 q rows. Q persistent in smem,
// stream K tiles -> S regs -> bias+online softmax -> P to smem (tf32+permc)
// -> stream V^T tiles -> O regs. Output rounded+permuted for out-projection.
// Smem: Qs 64KB | Ps 64KB | 2 stream slots 32KB = 160KB.
// ---------------------------------------------------------------------------
constexpr int SMEM_FLASH = 163840;
#define ATT_SCALE 0.08838834764831845f

__global__ __launch_bounds__(256, 1) void flash_kernel(
    const float* __restrict__ qr, const float* __restrict__ kr,
    const float* __restrict__ vt, const float* __restrict__ abias,
    float* __restrict__ outr)
{
    extern __shared__ float sm[];
    const uint32_t sb = su32(sm);
    __shared__ float rmax[128][4];
    __shared__ float rsum[128][4];

    const int tid = threadIdx.x, wid = tid >> 5, l = tid & 31;
    const int wm = wid >> 2, wn = wid & 3;
    const int bh = blockIdx.y, b = bh >> 5, h = bh & 31;
    const int q0 = blockIdx.x * 128;

    const float* qP = qr + ((long long)(b * SEQ + q0)) * DMODEL + h * HDIM;
    const float* kP = kr + (long long)b * SEQ * DMODEL + h * HDIM;
    const float* vP = vt + (long long)bh * HDIM * SEQ;
    const float* bP = abias + (long long)q0 * SEQ;
    float* oP = outr + ((long long)(b * SEQ + q0)) * DMODEL + h * HDIM;

    // load Q block: 4 slices of [128 rows][32 floats]
#pragma unroll
    for (int s = 0; s < 4; s++)
#pragma unroll
        for (int i = 0; i < 4; i++) {
            int ch = tid + i * 256, r = ch >> 3, c = ch & 7;
            cpa(sb + s * 16384 + r * 128 + ((c ^ ((r & 1) << 2)) << 4),
                qP + (long long)r * DMODEL + s * 32 + c * 4);
        }
    cpa_commit();

    const uint32_t stb = sb + 131072;   // 2 stream slots of 16KB
    auto fillB = [&](uint32_t dst, const float* src, int ld, int koff) {
#pragma unroll
        for (int i = 0; i < 4; i++) {
            int ch = tid + i * 256, r = ch >> 3, c = ch & 7;
            cpa(dst + r * 128 + ((c ^ ((r & 1) << 2)) << 4),
                src + (long long)r * ld + koff + c * 4);
        }
        cpa_commit();
    };

    float oacc[4][4][4] = {};
    float mrun[4][2], lrun[4][2];
#pragma unroll
    for (int mt = 0; mt < 4; mt++)
#pragma unroll
        for (int hh = 0; hh < 2; hh++) { mrun[mt][hh] = -1e30f; lrun[mt][hh] = 0.0f; }

    cpa_wait<0>();
    __syncthreads();

    for (int st = 0; st < 8; st++) {
        const int s0 = st * 128;
        float sacc[4][4][4] = {};

        // ---- S = Q K^T over 4 k-slices ----
        fillB(stb, kP + (long long)s0 * DMODEL, DMODEL, 0);
#pragma unroll
        for (int kt = 0; kt < 4; kt++) {
            if (kt < 3) {
                fillB(stb + ((kt + 1) & 1) * 16384, kP + (long long)s0 * DMODEL,
                      DMODEL, (kt + 1) * 32);
                cpa_wait<1>();
            } else cpa_wait<0>();
            __syncthreads();
            mma_core(sb + kt * 16384, stb + (kt & 1) * 16384, sacc, wm, wn, l);
            __syncthreads();
        }

        // prefetch V slice 0 while doing softmax
        fillB(stb, vP, SEQ, s0);

        // ---- scale + bias ----
#pragma unroll
        for (int mt = 0; mt < 4; mt++)
#pragma unroll
            for (int hh = 0; hh < 2; hh++) {
                int lrow = wm * 64 + mt * 16 + (l >> 2) + hh * 8;
                const float* br = bP + (long long)lrow * SEQ + s0;
#pragma unroll
                for (int nt = 0; nt < 4; nt++) {
                    int col = wn * 32 + nt * 8 + (l & 3) * 2;
                    float2 bv = *(const float2*)(br + col);
                    sacc[mt][nt][2 * hh]     = sacc[mt][nt][2 * hh] * ATT_SCALE + bv.x;
                    sacc[mt][nt][2 * hh + 1] = sacc[mt][nt][2 * hh + 1] * ATT_SCALE + bv.y;
                }
            }

        // ---- row max ----
#pragma unroll
        for (int mt = 0; mt < 4; mt++)
#pragma unroll
            for (int hh = 0; hh < 2; hh++) {
                int lrow = wm * 64 + mt * 16 + (l >> 2) + hh * 8;
                float mx = -1e30f;
#pragma unroll
                for (int nt = 0; nt < 4; nt++)
                    mx = fmaxf(mx, fmaxf(sacc[mt][nt][2 * hh], sacc[mt][nt][2 * hh + 1]));
                mx = fmaxf(mx, __shfl_xor_sync(~0u, mx, 1));
                mx = fmaxf(mx, __shfl_xor_sync(~0u, mx, 2));
                if ((l & 3) == 0) rmax[lrow][wn] = mx;
            }
        __syncthreads();

        float alpha[4][2], mnew[4][2];
#pragma unroll
        for (int mt = 0; mt < 4; mt++)
#pragma unroll
            for (int hh = 0; hh < 2; hh++) {
                int lrow = wm * 64 + mt * 16 + (l >> 2) + hh * 8;
                float Mt = fmaxf(fmaxf(rmax[lrow][0], rmax[lrow][1]),
                                 fmaxf(rmax[lrow][2], rmax[lrow][3]));
                float mn = fmaxf(mrun[mt][hh], Mt);
                alpha[mt][hh] = __expf(mrun[mt][hh] - mn);
                mnew[mt][hh] = mn;
                mrun[mt][hh] = mn;
            }

        // ---- P = exp(S - m), store to Ps (tf32 + permc), partial sums ----
#pragma unroll
        for (int mt = 0; mt < 4; mt++)
#pragma unroll
            for (int hh = 0; hh < 2; hh++) {
                int lrow = wm * 64 + mt * 16 + (l >> 2) + hh * 8;
                float ssum = 0.0f;
#pragma unroll
                for (int nt = 0; nt < 4; nt++) {
                    int col = wn * 32 + nt * 8 + (l & 3) * 2;
                    float p0 = __expf(sacc[mt][nt][2 * hh] - mnew[mt][hh]);
                    float p1 = __expf(sacc[mt][nt][2 * hh + 1] - mnew[mt][hh]);
                    ssum += p0 + p1;
#pragma unroll
                    for (int j = 0; j < 2; j++) {
                        int cc = col + j;
                        int w = permc(cc) & 31;
                        int widx = 16384 + (cc >> 5) * 4096 + lrow * 32 +
                                   (((w >> 2) ^ ((lrow & 1) << 2)) << 2) + (w & 3);
                        sm[widx] = tf32r(j == 0 ? p0 : p1);
                    }
                }
                ssum += __shfl_xor_sync(~0u, ssum, 1);
                ssum += __shfl_xor_sync(~0u, ssum, 2);
                if ((l & 3) == 0) rsum[lrow][wn] = ssum;
            }
        __syncthreads();

#pragma unroll
        for (int mt = 0; mt < 4; mt++)
#pragma unroll
            for (int hh = 0; hh < 2; hh++) {
                int lrow = wm * 64 + mt * 16 + (l >> 2) + hh * 8;
                float St = rsum[lrow][0] + rsum[lrow][1] + rsum[lrow][2] + rsum[lrow][3];
                lrun[mt][hh] = lrun[mt][hh] * alpha[mt][hh] + St;
                float a = alpha[mt][hh];
#pragma unroll
                for (int nt = 0; nt < 4; nt++) {
                    oacc[mt][nt][2 * hh] *= a;
                    oacc[mt][nt][2 * hh + 1] *= a;
                }
            }

        // ---- O += P V over 4 s-slices ----
#pragma unroll
        for (int kt = 0; kt < 4; kt++) {
            if (kt < 3) {
                fillB(stb + ((kt + 1) & 1) * 16384, vP, SEQ, s0 + (kt + 1) * 32);
                cpa_wait<1>();
            } else cpa_wait<0>();
            __syncthreads();
            mma_core(sb + 65536 + kt * 16384, stb + (kt & 1) * 16384, oacc, wm, wn, l);
            __syncthreads();
        }
    }

    // ---- epilogue: O/l, round+permute, store ----
#pragma unroll
    for (int mt = 0; mt < 4; mt++)
#pragma unroll
        for (int hh = 0; hh < 2; hh++) {
            int lrow = wm * 64 + mt * 16 + (l >> 2) + hh * 8;
            float inv = 1.0f / lrun[mt][hh];
            float* orow = oP + (long long)lrow * DMODEL;
#pragma unroll
            for (int nt = 0; nt < 4; nt++) {
                int d = wn * 32 + nt * 8 + (l & 3) * 2;
                orow[permc(d)]     = tf32r(oacc[mt][nt][2 * hh] * inv);
                orow[permc(d + 1)] = tf32r(oacc[mt][nt][2 * hh + 1] * inv);
            }
        }
}

// ---------------- prep kernels ----------------------------------------------
__global__ void rotary_table_kernel() {
    int idx = blockIdx.x * blockDim.x + threadIdx.x;
    if (idx >= SEQ * 16) return;
    int s = idx >> 4, i = idx & 15;
    double inv = pow(10000.0, -((double)(2 * i)) / 32.0);
    double ang = (double)(MAX_POS - SEQ + s) * inv;
    g_cos[idx] = (float)cos(ang);
    g_sin[idx] = (float)sin(ang);
}

__global__ void rp_kernel(const float* __restrict__ in, float* __restrict__ out, int n4) {
    int i = blockIdx.x * blockDim.x + threadIdx.x;
    if (i >= n4) return;
    int r = i >> 10, c = (i & 1023) * 4;
    float4 v = *(const float4*)(in + (long long)r * 4096 + c);
    float* o = out + (long long)r * 4096;
    o[permc(c)]     = tf32r(v.x);
    o[permc(c + 1)] = tf32r(v.y);
    o[permc(c + 2)] = tf32r(v.z);
    o[permc(c + 3)] = tf32r(v.w);
}

__global__ void wt_kernel(const float* __restrict__ w, float* __restrict__ out) {
    __shared__ float t[32][33];
    int k0 = blockIdx.y * 32, n0 = blockIdx.x * 32;
    int tx = threadIdx.x, ty = threadIdx.y;
#pragma unroll
    for (int i = 0; i < 4; i++)
        t[ty + i * 8][tx] = w[(long long)(k0 + ty + i * 8) * 4096 + n0 + tx];
    __syncthreads();
#pragma unroll
    for (int i = 0; i < 4; i++) {
        int n = n0 + ty + i * 8, k = k0 + tx;
        out[(long long)n * 4096 + permc(k)] = tf32r(t[tx][ty + i * 8]);
    }
}

__global__ void vtr_kernel(const float* __restrict__ v, float* __restrict__ vt) {
    __shared__ float t[32][33];
    int bh = blockIdx.z, b = bh >> 5, h = bh & 31;
    int s0 = blockIdx.x * 32, d0 = blockIdx.y * 32;
    int tx = threadIdx.x, ty = threadIdx.y;
    const float* src = v + (long long)b * SEQ * DMODEL + h * HDIM;
#pragma unroll
    for (int i = 0; i < 4; i++)
        t[ty + i * 8][tx] = src[(long long)(s0 + ty + i * 8) * DMODEL + d0 + tx];
    __syncthreads();
    float* dst = vt + (long long)bh * HDIM * SEQ;
#pragma unroll
    for (int i = 0; i < 4; i++) {
        int d = d0 + ty + i * 8, s = s0 + tx;
        dst[(long long)d * SEQ + permc(s)] = tf32r(t[tx][ty + i * 8]);
    }
}

// ---------------- host ------------------------------------------------------
extern "C" void kernel_launch(void* const* d_in, const int* in_sizes, int n_in,
                              void* d_out, int out_size) {
    (void)in_sizes; (void)n_in; (void)out_size;
    const float* x    = (const float*)d_in[0];
    const float* abia = (const float*)d_in[1];
    const float* wq   = (const float*)d_in[2];
    const float* bq   = (const float*)d_in[3];
    const float* wk   = (const float*)d_in[4];
    const float* bk   = (const float*)d_in[5];
    const float* wv   = (const float*)d_in[6];
    const float* bv   = (const float*)d_in[7];
    const float* wo   = (const float*)d_in[8];
    const float* bo   = (const float*)d_in[9];
    float* out = (float*)d_out;

    void* p;
    cudaGetSymbolAddress(&p, g_xr);  float* xr  = (float*)p;
    cudaGetSymbolAddress(&p, g_wqr); float* wqr = (float*)p;
    cudaGetSymbolAddress(&p, g_wkr); float* wkr = (float*)p;
    cudaGetSymbolAddress(&p, g_wvr); float* wvr = (float*)p;
    cudaGetSymbolAddress(&p, g_wor); float* wor = (float*)p;
    cudaGetSymbolAddress(&p, g_qr);  float* qr  = (float*)p;
    cudaGetSymbolAddress(&p, g_kr);  float* kr  = (float*)p;
    cudaGetSymbolAddress(&p, g_v);   float* v   = (float*)p;
    cudaGetSymbolAddress(&p, g_vt);  float* vt  = (float*)p;
    float* orr = xr;   // xr dead after QKV GEMMs -> reuse for flash output

    cudaFuncSetAttribute(gemm_kernel<1>, cudaFuncAttributeMaxDynamicSharedMemorySize, SMEM_GEMM);
    cudaFuncSetAttribute(gemm_kernel<3>, cudaFuncAttributeMaxDynamicSharedMemorySize, SMEM_GEMM);
    cudaFuncSetAttribute(flash_kernel,   cudaFuncAttributeMaxDynamicSharedMemorySize, SMEM_FLASH);

    rotary_table_kernel<<<(SEQ * 16 + 255) / 256, 256>>>();
    rp_kernel<<<(TOKENS * 1024 + 255) / 256, 256>>>(x, xr, TOKENS * 1024);
    {
        dim3 g(128, 128), b(32, 8);
        wt_kernel<<<g, b>>>(wq, wqr);
        wt_kernel<<<g, b>>>(wk, wkr);
        wt_kernel<<<g, b>>>(wv, wvr);
        wt_kernel<<<g, b>>>(wo, wor);
    }

    // QKV projections; q/k epilogues do bias+rotary+round+permute in place
    {
        dim3 grid(32, 32, 1);
        gemm_kernel<3><<<grid, 256, SMEM_GEMM>>>(xr, DMODEL, wqr, DMODEL, qr, DMODEL, DMODEL, bq);
        gemm_kernel<3><<<grid, 256, SMEM_GEMM>>>(xr, DMODEL, wkr, DMODEL, kr, DMODEL, DMODEL, bk);
        gemm_kernel<1><<<grid, 256, SMEM_GEMM>>>(xr, DMODEL, wvr, DMODEL, v,  DMODEL, DMODEL, bv);
    }

    vtr_kernel<<<dim3(32, 4, BATCHN * NHEAD), dim3(32, 8)>>>(v, vt);

    // fused attention (scores + softmax + PV), writes out-proj input directly
    flash_kernel<<<dim3(8, BATCHN * NHEAD), 256, SMEM_FLASH>>>(qr, kr, vt, abia, orr);

    // output projection
    gemm_kernel<1><<<dim3(32, 32, 1), 256, SMEM_GEMM>>>(orr, DMODEL, wor, DMODEL, out, DMODEL, DMODEL, bo);
}

// round 7
// speedup vs baseline: 3.4526x; 1.0731x over previous
#include <cuda_runtime.h>
#include <cstdint>
#include <math.h>

#define BATCHN 4
#define SEQ    1024
#define DMODEL 4096
#define NHEAD  32
#define HDIM   128
#define TOKENS 4096
#define MAX_POS 10000

// ---------------- scratch (device globals; malloc banned) ------------------
__device__ float g_xr [(size_t)TOKENS * DMODEL];    // rounded/permuted x (later: flash O out)
__device__ float g_wqr[(size_t)DMODEL * DMODEL];
__device__ float g_wkr[(size_t)DMODEL * DMODEL];
__device__ float g_wvr[(size_t)DMODEL * DMODEL];
__device__ float g_wor[(size_t)DMODEL * DMODEL];
__device__ float g_qr [(size_t)TOKENS * DMODEL];    // rotary+rounded+permuted Q
__device__ float g_kr [(size_t)TOKENS * DMODEL];
__device__ float g_vt [(size_t)BATCHN * NHEAD * HDIM * SEQ];  // V^T rounded/permuted
__device__ float g_cos[SEQ * 16];
__device__ float g_sin[SEQ * 16];

// ---------------- helpers ---------------------------------------------------
__device__ __forceinline__ uint32_t su32(const void* p) {
    return (uint32_t)__cvta_generic_to_shared(p);
}
__device__ __forceinline__ float tf32r(float x) {
    uint32_t u;
    asm("cvt.rna.tf32.f32 %0, %1;" : "=r"(u) : "f"(x));
    return __uint_as_float(u);
}
// permuted column: within each 16-group, col k stored at 4*(k%4) + (k%16)/4
__device__ __forceinline__ int permc(int k) {
    int kk = k & 15;
    return (k & ~15) | ((kk & 3) << 2) | (kk >> 2);
}
__device__ __forceinline__ void cpa(uint32_t s, const void* g) {
    asm volatile("cp.async.cg.shared.global [%0], [%1], 16;" :: "r"(s), "l"(g));
}
__device__ __forceinline__ void cpa_commit() {
    asm volatile("cp.async.commit_group;" ::: "memory");
}
template <int N> __device__ __forceinline__ void cpa_wait() {
    asm volatile("cp.async.wait_group %0;" :: "n"(N) : "memory");
}
__device__ __forceinline__ void lds4(uint32_t* v, uint32_t a) {
    asm volatile("ld.shared.v4.b32 {%0,%1,%2,%3}, [%4];"
                 : "=r"(v[0]), "=r"(v[1]), "=r"(v[2]), "=r"(v[3]) : "r"(a));
}
__device__ __forceinline__ void mma8(float* c, uint32_t a0, uint32_t a1, uint32_t a2,
                                     uint32_t a3, uint32_t b0, uint32_t b1) {
    asm volatile(
        "mma.sync.aligned.m16n8k8.row.col.f32.tf32.tf32.f32 "
        "{%0,%1,%2,%3},{%4,%5,%6,%7},{%8,%9},{%0,%1,%2,%3};"
        : "+f"(c[0]), "+f"(c[1]), "+f"(c[2]), "+f"(c[3])
        : "r"(a0), "r"(a1), "r"(a2), "r"(a3), "r"(b0), "r"(b1));
}

// shared 128x128x32 warp-tile mma core (8 warps 2x4, warp 64x32)
__device__ __forceinline__ void mma_core(uint32_t ab, uint32_t bb,
                                         float acc[4][4][4], int wm, int wn, int l) {
#pragma unroll
    for (int g = 0; g < 2; g++) {
        uint32_t bfr[4][4];
#pragma unroll
        for (int nt = 0; nt < 4; nt++) {
            int r = wn * 32 + nt * 8 + (l >> 2);
            lds4(bfr[nt], bb + r * 128 + (((g * 4 + (l & 3)) ^ ((r & 1) << 2)) << 4));
        }
#pragma unroll
        for (int mt = 0; mt < 4; mt++) {
            int r0 = wm * 64 + mt * 16 + (l >> 2), r1 = r0 + 8;
            uint32_t a0[4], a1[4];
            lds4(a0, ab + r0 * 128 + (((g * 4 + (l & 3)) ^ ((r0 & 1) << 2)) << 4));
            lds4(a1, ab + r1 * 128 + (((g * 4 + (l & 3)) ^ ((r1 & 1) << 2)) << 4));
#pragma unroll
            for (int nt = 0; nt < 4; nt++)
                mma8(acc[mt][nt], a0[0], a1[0], a0[1], a1[1], bfr[nt][0], bfr[nt][1]);
#pragma unroll
            for (int nt = 0; nt < 4; nt++)
                mma8(acc[mt][nt], a0[2], a1[2], a0[3], a1[3], bfr[nt][2], bfr[nt][3]);
        }
    }
}

constexpr int STAGES = 3;
constexpr int SMEM_GEMM = STAGES * 32768;   // 96KB

// supertiled raster: 32x32 tile grid, groups of 8 m-tiles
__device__ __forceinline__ void raster(int pid, int& m0, int& n0) {
    const int gs = 8 * 32;
    int gid = pid / gs, r = pid - gid * gs;
    m0 = (gid * 8 + (r & 7)) * 128;
    n0 = (r >> 3) * 128;
}

// GEMM mainloop: fills acc for tile (m0,n0); A,B already batch-offset
__device__ __forceinline__ void gemm_main(
    const float* A, int lda, const float* B, int ldb, int K,
    uint32_t sb, float acc[4][4][4], int tid, int wm, int wn, int l)
{
    const int nK = K / 32;
    auto fill = [&](int kt, int s) {
        const uint32_t ab = sb + s * 32768;
        const float* ag = A + kt * 32;
        const float* bg = B + kt * 32;
#pragma unroll
        for (int i = 0; i < 4; i++) {
            int ch = tid + i * 256, r = ch >> 3, c = ch & 7;
            cpa(ab + r * 128 + ((c ^ ((r & 1) << 2)) << 4),
                ag + (long long)r * lda + c * 4);
        }
#pragma unroll
        for (int i = 0; i < 4; i++) {
            int ch = tid + i * 256, r = ch >> 3, c = ch & 7;
            cpa(ab + 16384 + r * 128 + ((c ^ ((r & 1) << 2)) << 4),
                bg + (long long)r * ldb + c * 4);
        }
        cpa_commit();
    };
    for (int s = 0; s < STAGES - 1; s++) fill(s, s);
    for (int kt = 0; kt < nK; kt++) {
        cpa_wait<STAGES - 2>();
        __syncthreads();
        if (kt + STAGES - 1 < nK) fill(kt + STAGES - 1, (kt + STAGES - 1) % STAGES);
        else cpa_commit();
        const uint32_t ab = sb + (kt % STAGES) * 32768;
        mma_core(ab, ab + 16384, acc, wm, wn, l);
        __syncthreads();
    }
}

// ---------------------------------------------------------------------------
// Out-projection GEMM: C = A*B + biasN (plain fp32 store)
// ---------------------------------------------------------------------------
__global__ __launch_bounds__(256, 2) void gemm_out_kernel(
    const float* __restrict__ A, const float* __restrict__ B,
    float* __restrict__ C, const float* __restrict__ biasN)
{
    extern __shared__ float sm[];
    const uint32_t sb = su32(sm);
    const int tid = threadIdx.x, wid = tid >> 5, l = tid & 31;
    const int wm = wid >> 2, wn = wid & 3;
    int m0, n0; raster(blockIdx.x, m0, n0);

    float acc[4][4][4] = {};
    gemm_main(A + (long long)m0 * DMODEL, DMODEL, B + (long long)n0 * DMODEL, DMODEL,
              DMODEL, sb, acc, tid, wm, wn, l);

#pragma unroll
    for (int mt = 0; mt < 4; mt++)
#pragma unroll
        for (int h = 0; h < 2; h++) {
            const long long row = m0 + wm * 64 + mt * 16 + (l >> 2) + h * 8;
            float* cr = C + row * DMODEL;
#pragma unroll
            for (int nt = 0; nt < 4; nt++) {
                int col = n0 + wn * 32 + nt * 8 + (l & 3) * 2;
                float2 o = {acc[mt][nt][2 * h] + biasN[col],
                            acc[mt][nt][2 * h + 1] + biasN[col + 1]};
                *(float2*)(cr + col) = o;
            }
        }
}

// ---------------------------------------------------------------------------
// Fused QKV GEMM. z=0: Q (bias+rotary+round+perm), z=1: K (same), z=2: V
// (bias, then transposed write to vt[bh][d][s] rounded+permuted via smem).
// ---------------------------------------------------------------------------
__global__ __launch_bounds__(256, 2) void qkv_kernel(
    const float* __restrict__ xr,
    const float* __restrict__ wqr, const float* __restrict__ wkr,
    const float* __restrict__ wvr,
    float* __restrict__ qr, float* __restrict__ kr, float* __restrict__ vt,
    const float* __restrict__ bq, const float* __restrict__ bk,
    const float* __restrict__ bv)
{
    extern __shared__ float sm[];
    const uint32_t sb = su32(sm);
    const int tid = threadIdx.x, wid = tid >> 5, l = tid & 31;
    const int wm = wid >> 2, wn = wid & 3;
    const int z = blockIdx.z;
    int m0, n0; raster(blockIdx.x, m0, n0);

    const float* B = (z == 0) ? wqr : (z == 1) ? wkr : wvr;
    const float* biasN = (z == 0) ? bq : (z == 1) ? bk : bv;

    float acc[4][4][4] = {};
    gemm_main(xr + (long long)m0 * DMODEL, DMODEL, B + (long long)n0 * DMODEL, DMODEL,
              DMODEL, sb, acc, tid, wm, wn, l);

    if (z < 2) {
        float* C = (z == 0) ? qr : kr;
#pragma unroll
        for (int mt = 0; mt < 4; mt++)
#pragma unroll
            for (int h = 0; h < 2; h++) {
                const long long row = m0 + wm * 64 + mt * 16 + (l >> 2) + h * 8;
                float* cr = C + row * DMODEL;
                if (wn == 0) {
                    const int tok = (int)(row & (SEQ - 1));
                    const float* cs = g_cos + tok * 16;
                    const float* sn = g_sin + tok * 16;
#pragma unroll
                    for (int nt = 0; nt < 2; nt++) {
                        int i = nt * 8 + (l & 3) * 2;
                        int colr = n0 + i;
                        float re0 = acc[mt][nt][2 * h]     + biasN[colr];
                        float re1 = acc[mt][nt][2 * h + 1] + biasN[colr + 1];
                        float im0 = acc[mt][nt + 2][2 * h]     + biasN[colr + 16];
                        float im1 = acc[mt][nt + 2][2 * h + 1] + biasN[colr + 17];
                        float c0 = cs[i], s0 = sn[i], c1 = cs[i + 1], s1 = sn[i + 1];
                        int ob = n0 + 2 * i;
                        cr[permc(ob)]     = tf32r(re0 * c0 - im0 * s0);
                        cr[permc(ob + 1)] = tf32r(re0 * s0 + im0 * c0);
                        cr[permc(ob + 2)] = tf32r(re1 * c1 - im1 * s1);
                        cr[permc(ob + 3)] = tf32r(re1 * s1 + im1 * c1);
                    }
                } else {
#pragma unroll
                    for (int nt = 0; nt < 4; nt++) {
                        int col = n0 + wn * 32 + nt * 8 + (l & 3) * 2;
                        cr[permc(col)]     = tf32r(acc[mt][nt][2 * h] + biasN[col]);
                        cr[permc(col + 1)] = tf32r(acc[mt][nt][2 * h + 1] + biasN[col + 1]);
                    }
                }
            }
    } else {
        // V: stage bias-added tile [s][d] in smem (pitch 133), write transposed
        __syncthreads();   // mma stage buffers free now
#pragma unroll
        for (int mt = 0; mt < 4; mt++)
#pragma unroll
            for (int h = 0; h < 2; h++) {
                int lrow = wm * 64 + mt * 16 + (l >> 2) + h * 8;
#pragma unroll
                for (int nt = 0; nt < 4; nt++) {
                    int col = wn * 32 + nt * 8 + (l & 3) * 2;
                    sm[lrow * 133 + col]     = acc[mt][nt][2 * h] + biasN[n0 + col];
                    sm[lrow * 133 + col + 1] = acc[mt][nt][2 * h + 1] + biasN[n0 + col + 1];
                }
            }
        __syncthreads();
        const int b = m0 >> 10, sBase = m0 & 1023, hd = n0 >> 7;
        const int d = tid >> 1, sh = (tid & 1) << 6;
        float* dp = vt + ((long long)(b * NHEAD + hd) * HDIM + d) * SEQ + sBase + sh;
#pragma unroll
        for (int g16 = 0; g16 < 4; g16++)
#pragma unroll
            for (int a4 = 0; a4 < 4; a4++) {
                int s0 = sh + g16 * 16;
                float4 v;
                v.x = tf32r(sm[(s0 + a4) * 133 + d]);
                v.y = tf32r(sm[(s0 + 4 + a4) * 133 + d]);
                v.z = tf32r(sm[(s0 + 8 + a4) * 133 + d]);
                v.w = tf32r(sm[(s0 + 12 + a4) * 133 + d]);
                *(float4*)(dp + g16 * 16 + a4 * 4) = v;
            }
    }
}

// ---------------------------------------------------------------------------
// Flash attention (unchanged from round 6)
// ---------------------------------------------------------------------------
constexpr int SMEM_FLASH = 163840;
#define ATT_SCALE 0.08838834764831845f

__global__ __launch_bounds__(256, 1) void flash_kernel(
    const float* __restrict__ qr, const float* __restrict__ kr,
    const float* __restrict__ vt, const float* __restrict__ abias,
    float* __restrict__ outr)
{
    extern __shared__ float sm[];
    const uint32_t sb = su32(sm);
    __shared__ float rmax[128][4];
    __shared__ float rsum[128][4];

    const int tid = threadIdx.x, wid = tid >> 5, l = tid & 31;
    const int wm = wid >> 2, wn = wid & 3;
    const int bh = blockIdx.y, b = bh >> 5, h = bh & 31;
    const int q0 = blockIdx.x * 128;

    const float* qP = qr + ((long long)(b * SEQ + q0)) * DMODEL + h * HDIM;
    const float* kP = kr + (long long)b * SEQ * DMODEL + h * HDIM;
    const float* vP = vt + (long long)bh * HDIM * SEQ;
    const float* bP = abias + (long long)q0 * SEQ;
    float* oP = outr + ((long long)(b * SEQ + q0)) * DMODEL + h * HDIM;

#pragma unroll
    for (int s = 0; s < 4; s++)
#pragma unroll
        for (int i = 0; i < 4; i++) {
            int ch = tid + i * 256, r = ch >> 3, c = ch & 7;
            cpa(sb + s * 16384 + r * 128 + ((c ^ ((r & 1) << 2)) << 4),
                qP + (long long)r * DMODEL + s * 32 + c * 4);
        }
    cpa_commit();

    const uint32_t stb = sb + 131072;
    auto fillB = [&](uint32_t dst, const float* src, int ld, int koff) {
#pragma unroll
        for (int i = 0; i < 4; i++) {
            int ch = tid + i * 256, r = ch >> 3, c = ch & 7;
            cpa(dst + r * 128 + ((c ^ ((r & 1) << 2)) << 4),
                src + (long long)r * ld + koff + c * 4);
        }
        cpa_commit();
    };

    float oacc[4][4][4] = {};
    float mrun[4][2], lrun[4][2];
#pragma unroll
    for (int mt = 0; mt < 4; mt++)
#pragma unroll
        for (int hh = 0; hh < 2; hh++) { mrun[mt][hh] = -1e30f; lrun[mt][hh] = 0.0f; }

    cpa_wait<0>();
    __syncthreads();

    for (int st = 0; st < 8; st++) {
        const int s0 = st * 128;
        float sacc[4][4][4] = {};

        fillB(stb, kP + (long long)s0 * DMODEL, DMODEL, 0);
#pragma unroll
        for (int kt = 0; kt < 4; kt++) {
            if (kt < 3) {
                fillB(stb + ((kt + 1) & 1) * 16384, kP + (long long)s0 * DMODEL,
                      DMODEL, (kt + 1) * 32);
                cpa_wait<1>();
            } else cpa_wait<0>();
            __syncthreads();
            mma_core(sb + kt * 16384, stb + (kt & 1) * 16384, sacc, wm, wn, l);
            __syncthreads();
        }

        fillB(stb, vP, SEQ, s0);

#pragma unroll
        for (int mt = 0; mt < 4; mt++)
#pragma unroll
            for (int hh = 0; hh < 2; hh++) {
                int lrow = wm * 64 + mt * 16 + (l >> 2) + hh * 8;
                const float* br = bP + (long long)lrow * SEQ + s0;
#pragma unroll
                for (int nt = 0; nt < 4; nt++) {
                    int col = wn * 32 + nt * 8 + (l & 3) * 2;
                    float2 bv = *(const float2*)(br + col);
                    sacc[mt][nt][2 * hh]     = sacc[mt][nt][2 * hh] * ATT_SCALE + bv.x;
                    sacc[mt][nt][2 * hh + 1] = sacc[mt][nt][2 * hh + 1] * ATT_SCALE + bv.y;
                }
            }

#pragma unroll
        for (int mt = 0; mt < 4; mt++)
#pragma unroll
            for (int hh = 0; hh < 2; hh++) {
                int lrow = wm * 64 + mt * 16 + (l >> 2) + hh * 8;
                float mx = -1e30f;
#pragma unroll
                for (int nt = 0; nt < 4; nt++)
                    mx = fmaxf(mx, fmaxf(sacc[mt][nt][2 * hh], sacc[mt][nt][2 * hh + 1]));
                mx = fmaxf(mx, __shfl_xor_sync(~0u, mx, 1));
                mx = fmaxf(mx, __shfl_xor_sync(~0u, mx, 2));
                if ((l & 3) == 0) rmax[lrow][wn] = mx;
            }
        __syncthreads();

        float alpha[4][2], mnew[4][2];
#pragma unroll
        for (int mt = 0; mt < 4; mt++)
#pragma unroll
            for (int hh = 0; hh < 2; hh++) {
                int lrow = wm * 64 + mt * 16 + (l >> 2) + hh * 8;
                float Mt = fmaxf(fmaxf(rmax[lrow][0], rmax[lrow][1]),
                                 fmaxf(rmax[lrow][2], rmax[lrow][3]));
                float mn = fmaxf(mrun[mt][hh], Mt);
                alpha[mt][hh] = __expf(mrun[mt][hh] - mn);
                mnew[mt][hh] = mn;
                mrun[mt][hh] = mn;
            }

#pragma unroll
        for (int mt = 0; mt < 4; mt++)
#pragma unroll
            for (int hh = 0; hh < 2; hh++) {
                int lrow = wm * 64 + mt * 16 + (l >> 2) + hh * 8;
                float ssum = 0.0f;
#pragma unroll
                for (int nt = 0; nt < 4; nt++) {
                    int col = wn * 32 + nt * 8 + (l & 3) * 2;
                    float p0 = __expf(sacc[mt][nt][2 * hh] - mnew[mt][hh]);
                    float p1 = __expf(sacc[mt][nt][2 * hh + 1] - mnew[mt][hh]);
                    ssum += p0 + p1;
#pragma unroll
                    for (int j = 0; j < 2; j++) {
                        int cc = col + j;
                        int w = permc(cc) & 31;
                        int widx = 16384 + (cc >> 5) * 4096 + lrow * 32 +
                                   (((w >> 2) ^ ((lrow & 1) << 2)) << 2) + (w & 3);
                        sm[widx] = tf32r(j == 0 ? p0 : p1);
                    }
                }
                ssum += __shfl_xor_sync(~0u, ssum, 1);
                ssum += __shfl_xor_sync(~0u, ssum, 2);
                if ((l & 3) == 0) rsum[lrow][wn] = ssum;
            }
        __syncthreads();

#pragma unroll
        for (int mt = 0; mt < 4; mt++)
#pragma unroll
            for (int hh = 0; hh < 2; hh++) {
                int lrow = wm * 64 + mt * 16 + (l >> 2) + hh * 8;
                float St = rsum[lrow][0] + rsum[lrow][1] + rsum[lrow][2] + rsum[lrow][3];
                lrun[mt][hh] = lrun[mt][hh] * alpha[mt][hh] + St;
                float a = alpha[mt][hh];
#pragma unroll
                for (int nt = 0; nt < 4; nt++) {
                    oacc[mt][nt][2 * hh] *= a;
                    oacc[mt][nt][2 * hh + 1] *= a;
                }
            }

#pragma unroll
        for (int kt = 0; kt < 4; kt++) {
            if (kt < 3) {
                fillB(stb + ((kt + 1) & 1) * 16384, vP, SEQ, s0 + (kt + 1) * 32);
                cpa_wait<1>();
            } else cpa_wait<0>();
            __syncthreads();
            mma_core(sb + 65536 + kt * 16384, stb + (kt & 1) * 16384, oacc, wm, wn, l);
            __syncthreads();
        }
    }

#pragma unroll
    for (int mt = 0; mt < 4; mt++)
#pragma unroll
        for (int hh = 0; hh < 2; hh++) {
            int lrow = wm * 64 + mt * 16 + (l >> 2) + hh * 8;
            float inv = 1.0f / lrun[mt][hh];
            float* orow = oP + (long long)lrow * DMODEL;
#pragma unroll
            for (int nt = 0; nt < 4; nt++) {
                int d = wn * 32 + nt * 8 + (l & 3) * 2;
                orow[permc(d)]     = tf32r(oacc[mt][nt][2 * hh] * inv);
                orow[permc(d + 1)] = tf32r(oacc[mt][nt][2 * hh + 1] * inv);
            }
        }
}

// ---------------- prep kernels ----------------------------------------------
__global__ void rotary_table_kernel() {
    int idx = blockIdx.x * blockDim.x + threadIdx.x;
    if (idx >= SEQ * 16) return;
    int s = idx >> 4, i = idx & 15;
    double inv = pow(10000.0, -((double)(2 * i)) / 32.0);
    double ang = (double)(MAX_POS - SEQ + s) * inv;
    g_cos[idx] = (float)cos(ang);
    g_sin[idx] = (float)sin(ang);
}

__global__ void rp_kernel(const float* __restrict__ in, float* __restrict__ out, int n4) {
    int i = blockIdx.x * blockDim.x + threadIdx.x;
    if (i >= n4) return;
    int r = i >> 10, c = (i & 1023) * 4;
    float4 v = *(const float4*)(in + (long long)r * 4096 + c);
    float* o = out + (long long)r * 4096;
    o[permc(c)]     = tf32r(v.x);
    o[permc(c + 1)] = tf32r(v.y);
    o[permc(c + 2)] = tf32r(v.z);
    o[permc(c + 3)] = tf32r(v.w);
}

// all 4 weights in one launch (z selects)
__global__ void wt_all_kernel(const float* __restrict__ wq, const float* __restrict__ wk,
                              const float* __restrict__ wv, const float* __restrict__ wo,
                              float* __restrict__ oq, float* __restrict__ ok,
                              float* __restrict__ ov, float* __restrict__ oo) {
    __shared__ float t[32][33];
    const int z = blockIdx.z;
    const float* w = (z == 0) ? wq : (z == 1) ? wk : (z == 2) ? wv : wo;
    float* o = (z == 0) ? oq : (z == 1) ? ok : (z == 2) ? ov : oo;
    int k0 = blockIdx.y * 32, n0 = blockIdx.x * 32;
    int tx = threadIdx.x, ty = threadIdx.y;
#pragma unroll
    for (int i = 0; i < 4; i++)
        t[ty + i * 8][tx] = w[(long long)(k0 + ty + i * 8) * 4096 + n0 + tx];
    __syncthreads();
#pragma unroll
    for (int i = 0; i < 4; i++) {
        int n = n0 + ty + i * 8, k = k0 + tx;
        o[(long long)n * 4096 + permc(k)] = tf32r(t[tx][ty + i * 8]);
    }
}

// ---------------- host ------------------------------------------------------
extern "C" void kernel_launch(void* const* d_in, const int* in_sizes, int n_in,
                              void* d_out, int out_size) {
    (void)in_sizes; (void)n_in; (void)out_size;
    const float* x    = (const float*)d_in[0];
    const float* abia = (const float*)d_in[1];
    const float* wq   = (const float*)d_in[2];
    const float* bq   = (const float*)d_in[3];
    const float* wk   = (const float*)d_in[4];
    const float* bk   = (const float*)d_in[5];
    const float* wv   = (const float*)d_in[6];
    const float* bv   = (const float*)d_in[7];
    const float* wo   = (const float*)d_in[8];
    const float* bo   = (const float*)d_in[9];
    float* out = (float*)d_out;

    void* p;
    cudaGetSymbolAddress(&p, g_xr);  float* xr  = (float*)p;
    cudaGetSymbolAddress(&p, g_wqr); float* wqr = (float*)p;
    cudaGetSymbolAddress(&p, g_wkr); float* wkr = (float*)p;
    cudaGetSymbolAddress(&p, g_wvr); float* wvr = (float*)p;
    cudaGetSymbolAddress(&p, g_wor); float* wor = (float*)p;
    cudaGetSymbolAddress(&p, g_qr);  float* qr  = (float*)p;
    cudaGetSymbolAddress(&p, g_kr);  float* kr  = (float*)p;
    cudaGetSymbolAddress(&p, g_vt);  float* vt  = (float*)p;
    float* orr = xr;   // xr dead after QKV GEMMs -> reuse for flash output

    cudaFuncSetAttribute(gemm_out_kernel, cudaFuncAttributeMaxDynamicSharedMemorySize, SMEM_GEMM);
    cudaFuncSetAttribute(qkv_kernel,      cudaFuncAttributeMaxDynamicSharedMemorySize, SMEM_GEMM);
    cudaFuncSetAttribute(flash_kernel,    cudaFuncAttributeMaxDynamicSharedMemorySize, SMEM_FLASH);

    // 1-3: prep
    rotary_table_kernel<<<(SEQ * 16 + 255) / 256, 256>>>();
    rp_kernel<<<(TOKENS * 1024 + 255) / 256, 256>>>(x, xr, TOKENS * 1024);
    wt_all_kernel<<<dim3(128, 128, 4), dim3(32, 8)>>>(wq, wk, wv, wo, wqr, wkr, wvr, wor);

    // 4: fused QKV (V written transposed to vt directly)
    qkv_kernel<<<dim3(1024, 1, 3), 256, SMEM_GEMM>>>(
        xr, wqr, wkr, wvr, qr, kr, vt, bq, bk, bv);

    // 5: fused attention
    flash_kernel<<<dim3(8, BATCHN * NHEAD), 256, SMEM_FLASH>>>(qr, kr, vt, abia, orr);

    // 6: output projection (ncu -s 5 captures this launch)
    gemm_out_kernel<<<dim3(1024), 256, SMEM_GEMM>>>(orr, wor, out, bo);
}